// round 3
// baseline (speedup 1.0000x reference)
#include <cuda_runtime.h>
#include <cstddef>

#define NN_   4000
#define TT_   64
#define FF_   128
#define HH_   128
#define TH_   384
#define KK_   32
#define EE_   64

// ---------------- scratch (static device globals; no allocation) --------------
__device__ float g_xn [(size_t)NN_ * TT_ * FF_];
__device__ float g_xg [(size_t)NN_ * TT_ * TH_];
__device__ float g_h1 [(size_t)NN_ * TT_ * HH_];
__device__ float g_es [NN_ * HH_];
__device__ float g_t1 [NN_ * HH_];
__device__ float g_ep [NN_ * HH_];
__device__ float g_er [NN_ * HH_];
__device__ float g_eh [NN_ * HH_];
__device__ float g_eres[NN_ * HH_];
__device__ float g_ea [NN_ * HH_];
__device__ float g_beta[NN_ * KK_];
__device__ float g_m1 [EE_ * HH_];
__device__ float g_m2 [KK_ * HH_];
__device__ float g_idn [NN_];
__device__ float g_ide [EE_];
__device__ float g_isdn[NN_];
__device__ float g_ide2[KK_];

// ---------------- packed f32x2 helpers ----------------
__device__ __forceinline__ unsigned long long pk2(float lo, float hi) {
    unsigned long long r;
    asm("mov.b64 %0, {%1, %2};" : "=l"(r) : "f"(lo), "f"(hi));
    return r;
}
__device__ __forceinline__ unsigned long long dup2(float v) {
    unsigned long long r;
    asm("mov.b64 %0, {%1, %1};" : "=l"(r) : "f"(v));
    return r;
}
__device__ __forceinline__ void upk2(unsigned long long v, float& lo, float& hi) {
    asm("mov.b64 {%0, %1}, %2;" : "=f"(lo), "=f"(hi) : "l"(v));
}
__device__ __forceinline__ void fma2(unsigned long long& d, unsigned long long a, unsigned long long b) {
    asm("fma.rn.f32x2 %0, %1, %2, %0;" : "+l"(d) : "l"(a), "l"(b));
}
__device__ __forceinline__ float sigf(float x) {
    return __fdividef(1.f, 1.f + __expf(-x));
}

// ================= LayerNorm: one warp per 128-wide row ===================
__global__ void __launch_bounds__(256) ln_kernel(const float* __restrict__ x,
                                                 const float* __restrict__ g,
                                                 const float* __restrict__ b,
                                                 float* __restrict__ y) {
    int warp = threadIdx.x >> 5, lane = threadIdx.x & 31;
    size_t row = (size_t)blockIdx.x * 8 + warp;
    const float* xr = x + row * FF_;
    float4 v = *(const float4*)&xr[lane * 4];
    float s  = v.x + v.y + v.z + v.w;
    float ss = v.x * v.x + v.y * v.y + v.z * v.z + v.w * v.w;
    #pragma unroll
    for (int o = 16; o > 0; o >>= 1) {
        s  += __shfl_xor_sync(0xffffffffu, s,  o);
        ss += __shfl_xor_sync(0xffffffffu, ss, o);
    }
    float mean = s * (1.f / 128.f);
    float var  = ss * (1.f / 128.f) - mean * mean;
    float rstd = rsqrtf(var + 1e-5f);
    float4 gv = *(const float4*)&g[lane * 4];
    float4 bv = *(const float4*)&b[lane * 4];
    float4 o4;
    o4.x = (v.x - mean) * rstd * gv.x + bv.x;
    o4.y = (v.y - mean) * rstd * gv.y + bv.y;
    o4.z = (v.z - mean) * rstd * gv.z + bv.z;
    o4.w = (v.w - mean) * rstd * gv.w + bv.w;
    *(float4*)&y[row * FF_ + lane * 4] = o4;
}

// ========== SGEMM  C[M,NNout] = A[M,128] @ W[NNout,128]^T (+bias)(+lrelu) =====
#define AS_LD 130
#define BS_LD 132
#define GEMM_SMEM ((size_t)(128 * AS_LD + 128 * BS_LD) * 4)

__global__ void __launch_bounds__(256) gemm128(const float* __restrict__ A,
                                               const float* __restrict__ W,
                                               const float* __restrict__ bias,
                                               float* __restrict__ C,
                                               int M, int NNout, int act) {
    extern __shared__ float sm[];
    float* As = sm;
    float* Bs = sm + 128 * AS_LD;
    int tid = threadIdx.x;
    int mBase = blockIdx.x * 128;
    int nBase = blockIdx.y * 128;

    #pragma unroll
    for (int i = 0; i < 16; ++i) {
        int lin = tid + i * 256;
        int m = lin >> 5, k4 = lin & 31;
        float4 v = make_float4(0.f, 0.f, 0.f, 0.f);
        if (mBase + m < M) v = *(const float4*)&A[(size_t)(mBase + m) * 128 + k4 * 4];
        float* dst = &As[m * AS_LD + k4 * 4];
        dst[0] = v.x; dst[1] = v.y; dst[2] = v.z; dst[3] = v.w;
    }
    {
        int ng = tid >> 5, k4 = tid & 31;
        #pragma unroll
        for (int i = 0; i < 4; ++i) {
            int nr = (ng + i * 8) * 4;
            float4 w0 = *(const float4*)&W[(size_t)(nBase + nr + 0) * 128 + k4 * 4];
            float4 w1 = *(const float4*)&W[(size_t)(nBase + nr + 1) * 128 + k4 * 4];
            float4 w2 = *(const float4*)&W[(size_t)(nBase + nr + 2) * 128 + k4 * 4];
            float4 w3 = *(const float4*)&W[(size_t)(nBase + nr + 3) * 128 + k4 * 4];
            *(float4*)&Bs[(k4 * 4 + 0) * BS_LD + nr] = make_float4(w0.x, w1.x, w2.x, w3.x);
            *(float4*)&Bs[(k4 * 4 + 1) * BS_LD + nr] = make_float4(w0.y, w1.y, w2.y, w3.y);
            *(float4*)&Bs[(k4 * 4 + 2) * BS_LD + nr] = make_float4(w0.z, w1.z, w2.z, w3.z);
            *(float4*)&Bs[(k4 * 4 + 3) * BS_LD + nr] = make_float4(w0.w, w1.w, w2.w, w3.w);
        }
    }
    __syncthreads();

    int tx = tid & 15, ty = tid >> 4;
    int c0 = tx * 8, r0 = ty * 8;

    unsigned long long acc[8][4];
    #pragma unroll
    for (int i = 0; i < 8; ++i)
        #pragma unroll
        for (int q = 0; q < 4; ++q) acc[i][q] = pk2(0.f, 0.f);

    #pragma unroll 4
    for (int k = 0; k < 128; ++k) {
        float a[8];
        #pragma unroll
        for (int i = 0; i < 8; ++i) a[i] = As[(r0 + i) * AS_LD + k];
        ulonglong2 b01 = *(const ulonglong2*)&Bs[k * BS_LD + c0];
        ulonglong2 b23 = *(const ulonglong2*)&Bs[k * BS_LD + c0 + 4];
        #pragma unroll
        for (int i = 0; i < 8; ++i) {
            unsigned long long ad = dup2(a[i]);
            fma2(acc[i][0], ad, b01.x);
            fma2(acc[i][1], ad, b01.y);
            fma2(acc[i][2], ad, b23.x);
            fma2(acc[i][3], ad, b23.y);
        }
    }

    float bv[8];
    #pragma unroll
    for (int j = 0; j < 8; ++j) bv[j] = bias ? bias[nBase + c0 + j] : 0.f;

    #pragma unroll
    for (int i = 0; i < 8; ++i) {
        int gm = mBase + r0 + i;
        if (gm >= M) continue;
        float o[8];
        #pragma unroll
        for (int q = 0; q < 4; ++q) upk2(acc[i][q], o[2 * q], o[2 * q + 1]);
        #pragma unroll
        for (int j = 0; j < 8; ++j) {
            o[j] += bv[j];
            if (act) o[j] = o[j] > 0.f ? o[j] : 0.01f * o[j];
        }
        *(float4*)&C[(size_t)gm * NNout + nBase + c0]     = make_float4(o[0], o[1], o[2], o[3]);
        *(float4*)&C[(size_t)gm * NNout + nBase + c0 + 4] = make_float4(o[4], o[5], o[6], o[7]);
    }
}

// ================== GRU scan: one CTA owns 32 rows for all 64 steps ===========
#define SCAN_SMEM ((size_t)(128 * TH_ + 32 * HH_) * 4)

__global__ void __launch_bounds__(256) gru_scan(const float* __restrict__ xg,
                                                const float* __restrict__ Whh,
                                                const float* __restrict__ bhh,
                                                float* __restrict__ hseq,
                                                float* __restrict__ hlast) {
    extern __shared__ float sm[];
    float* Wsm = sm;               // [k][384]  (k-major transpose of W_hh)
    float* hs  = sm + 128 * TH_;   // [r][128]
    int tid = threadIdx.x;

    #pragma unroll 4
    for (int i = 0; i < 48; ++i) {
        int lin = tid + i * 256;
        int j = lin >> 5, k4 = lin & 31;
        float4 v = *(const float4*)&Whh[j * 128 + k4 * 4];
        Wsm[(k4 * 4 + 0) * TH_ + j] = v.x;
        Wsm[(k4 * 4 + 1) * TH_ + j] = v.y;
        Wsm[(k4 * 4 + 2) * TH_ + j] = v.z;
        Wsm[(k4 * 4 + 3) * TH_ + j] = v.w;
    }
    for (int i = tid; i < 32 * HH_; i += 256) hs[i] = 0.f;

    int tn = tid & 31, tm = tid >> 5;
    int c0 = tn * 4, r0 = tm * 4;
    int n0 = blockIdx.x * 32;

    unsigned long long bpk[3][2];
    #pragma unroll
    for (int g = 0; g < 3; ++g) {
        bpk[g][0] = pk2(bhh[g * 128 + c0 + 0], bhh[g * 128 + c0 + 1]);
        bpk[g][1] = pk2(bhh[g * 128 + c0 + 2], bhh[g * 128 + c0 + 3]);
    }
    float hprev[4][4];
    #pragma unroll
    for (int ri = 0; ri < 4; ++ri)
        #pragma unroll
        for (int cc = 0; cc < 4; ++cc) hprev[ri][cc] = 0.f;

    __syncthreads();

    for (int t = 0; t < TT_; ++t) {
        float4 xv[3][4];
        #pragma unroll
        for (int ri = 0; ri < 4; ++ri)
            #pragma unroll
            for (int g = 0; g < 3; ++g)
                xv[g][ri] = *(const float4*)&xg[(size_t)(n0 + r0 + ri) * (TT_ * TH_) + t * TH_ + g * 128 + c0];

        unsigned long long acc[3][2][4];
        #pragma unroll
        for (int g = 0; g < 3; ++g)
            #pragma unroll
            for (int p = 0; p < 2; ++p)
                #pragma unroll
                for (int r = 0; r < 4; ++r) acc[g][p][r] = bpk[g][p];

        #pragma unroll 8
        for (int k = 0; k < 128; ++k) {
            const float* hk = &hs[r0 * 128 + k];
            unsigned long long a0 = dup2(hk[0]);
            unsigned long long a1 = dup2(hk[128]);
            unsigned long long a2 = dup2(hk[256]);
            unsigned long long a3 = dup2(hk[384]);
            const float* wk = &Wsm[k * TH_ + c0];
            ulonglong2 w0 = *(const ulonglong2*)(wk);
            ulonglong2 w1 = *(const ulonglong2*)(wk + 128);
            ulonglong2 w2 = *(const ulonglong2*)(wk + 256);
            fma2(acc[0][0][0], a0, w0.x); fma2(acc[0][1][0], a0, w0.y);
            fma2(acc[0][0][1], a1, w0.x); fma2(acc[0][1][1], a1, w0.y);
            fma2(acc[0][0][2], a2, w0.x); fma2(acc[0][1][2], a2, w0.y);
            fma2(acc[0][0][3], a3, w0.x); fma2(acc[0][1][3], a3, w0.y);
            fma2(acc[1][0][0], a0, w1.x); fma2(acc[1][1][0], a0, w1.y);
            fma2(acc[1][0][1], a1, w1.x); fma2(acc[1][1][1], a1, w1.y);
            fma2(acc[1][0][2], a2, w1.x); fma2(acc[1][1][2], a2, w1.y);
            fma2(acc[1][0][3], a3, w1.x); fma2(acc[1][1][3], a3, w1.y);
            fma2(acc[2][0][0], a0, w2.x); fma2(acc[2][1][0], a0, w2.y);
            fma2(acc[2][0][1], a1, w2.x); fma2(acc[2][1][1], a1, w2.y);
            fma2(acc[2][0][2], a2, w2.x); fma2(acc[2][1][2], a2, w2.y);
            fma2(acc[2][0][3], a3, w2.x); fma2(acc[2][1][3], a3, w2.y);
        }
        __syncthreads();

        #pragma unroll
        for (int ri = 0; ri < 4; ++ri) {
            float hr[4], hz[4], hn_[4];
            upk2(acc[0][0][ri], hr[0], hr[1]);   upk2(acc[0][1][ri], hr[2], hr[3]);
            upk2(acc[1][0][ri], hz[0], hz[1]);   upk2(acc[1][1][ri], hz[2], hz[3]);
            upk2(acc[2][0][ri], hn_[0], hn_[1]); upk2(acc[2][1][ri], hn_[2], hn_[3]);
            float xr[4]  = {xv[0][ri].x, xv[0][ri].y, xv[0][ri].z, xv[0][ri].w};
            float xz[4]  = {xv[1][ri].x, xv[1][ri].y, xv[1][ri].z, xv[1][ri].w};
            float xn4[4] = {xv[2][ri].x, xv[2][ri].y, xv[2][ri].z, xv[2][ri].w};
            float hnew[4];
            #pragma unroll
            for (int cc = 0; cc < 4; ++cc) {
                float rg = sigf(xr[cc] + hr[cc]);
                float zg = sigf(xz[cc] + hz[cc]);
                float ng = tanhf(xn4[cc] + rg * hn_[cc]);
                hnew[cc] = (1.f - zg) * ng + zg * hprev[ri][cc];
                hprev[ri][cc] = hnew[cc];
            }
            *(float4*)&hs[(r0 + ri) * 128 + c0] = make_float4(hnew[0], hnew[1], hnew[2], hnew[3]);
            if (hseq)
                *(float4*)&hseq[(size_t)(n0 + r0 + ri) * (TT_ * HH_) + t * HH_ + c0] =
                    make_float4(hnew[0], hnew[1], hnew[2], hnew[3]);
        }
        __syncthreads();
    }

    if (hlast)
        #pragma unroll
        for (int ri = 0; ri < 4; ++ri)
            *(float4*)&hlast[(size_t)(n0 + r0 + ri) * HH_ + c0] =
                make_float4(hprev[ri][0], hprev[ri][1], hprev[ri][2], hprev[ri][3]);
}

// ====================== small post-GRU hypergraph kernels =====================
__global__ void degrees_kernel(const int* __restrict__ ind, float* __restrict__ inv_dn,
                               float* __restrict__ inv_de) {
    if (blockIdx.x == 0) {
        int e = threadIdx.x;
        if (e < EE_) {
            int s = 0;
            for (int n = 0; n < NN_; ++n) s += ind[n * EE_ + e];
            inv_de[e] = s > 0 ? __fdividef(1.f, (float)s) : 0.f;
        }
    } else {
        int n = (blockIdx.x - 1) * 256 + threadIdx.x;
        if (n < NN_) {
            int s = 0;
            #pragma unroll 8
            for (int e = 0; e < EE_; ++e) s += ind[n * EE_ + e];
            inv_dn[n] = s > 0 ? __fdividef(1.f, (float)s) : 0.f;
        }
    }
}

__global__ void prior_m_kernel(const int* __restrict__ ind, const float* __restrict__ xW,
                               const float* __restrict__ inv_de, float* __restrict__ m1) {
    int e = blockIdx.x, j = threadIdx.x;
    float acc = 0.f;
    #pragma unroll 4
    for (int n = 0; n < NN_; ++n)
        acc += (float)ind[n * EE_ + e] * xW[n * HH_ + j];
    m1[e * HH_ + j] = acc * inv_de[e];
}

__global__ void prior_out_kernel(const int* __restrict__ ind, const float* __restrict__ m1,
                                 const float* __restrict__ inv_dn, const float* __restrict__ bp,
                                 const float* __restrict__ es, float* __restrict__ ep,
                                 float* __restrict__ er) {
    __shared__ float ms[EE_ * HH_];
    int n = blockIdx.x, j = threadIdx.x;
    for (int i = j; i < EE_ * HH_; i += 128) ms[i] = m1[i];
    __syncthreads();
    float acc = 0.f;
    #pragma unroll 8
    for (int e = 0; e < EE_; ++e)
        acc += (float)ind[n * EE_ + e] * ms[e * HH_ + j];
    float v = acc * inv_dn[n] + bp[j];
    v = v > 0.f ? v : 0.01f * v;
    ep[n * HH_ + j] = v;
    er[n * HH_ + j] = es[n * HH_ + j] - v;
}

__global__ void beta_kernel(const float* __restrict__ er, const float* __restrict__ proto,
                            float* __restrict__ beta, float* __restrict__ isdn) {
    __shared__ float ers[HH_];
    __shared__ float sb[KK_];
    int n = blockIdx.x, tid = threadIdx.x;
    ers[tid] = er[n * HH_ + tid];
    __syncthreads();
    int k = tid >> 2, p = tid & 3;
    float acc = 0.f;
    #pragma unroll 8
    for (int j = p; j < HH_; j += 4)
        acc += ers[j] * __ldg(&proto[k * HH_ + j]);
    acc += __shfl_xor_sync(0xffffffffu, acc, 1);
    acc += __shfl_xor_sync(0xffffffffu, acc, 2);
    if (p == 0) {
        float bv = sigf(acc);
        beta[n * KK_ + k] = bv;
        sb[k] = bv;
    }
    __syncthreads();
    if (tid < 32) {
        float v = sb[tid];
        #pragma unroll
        for (int o = 16; o > 0; o >>= 1) v += __shfl_xor_sync(0xffffffffu, v, o);
        if (tid == 0) isdn[n] = v > 0.f ? rsqrtf(v) : 0.f;
    }
}

__global__ void de2_kernel(const float* __restrict__ beta, float* __restrict__ inv_de2) {
    int k = blockIdx.x, tid = threadIdx.x;
    float s = 0.f;
    for (int n = tid; n < NN_; n += 256) s += beta[n * KK_ + k];
    __shared__ float red[256];
    red[tid] = s;
    __syncthreads();
    for (int o = 128; o > 0; o >>= 1) {
        if (tid < o) red[tid] += red[tid + o];
        __syncthreads();
    }
    if (tid == 0) inv_de2[k] = red[0] > 0.f ? __fdividef(1.f, red[0]) : 0.f;
}

__global__ void soft_m_kernel(const float* __restrict__ beta, const float* __restrict__ y,
                              const float* __restrict__ inv_de2, float* __restrict__ m2) {
    int k = blockIdx.x, j = threadIdx.x;
    float acc = 0.f;
    #pragma unroll 4
    for (int n = 0; n < NN_; ++n)
        acc += beta[n * KK_ + k] * y[n * HH_ + j];
    m2[k * HH_ + j] = acc * inv_de2[k];
}

__global__ void soft_out_kernel(const float* __restrict__ beta, const float* __restrict__ m2,
                                const float* __restrict__ isdn, const float* __restrict__ er,
                                float* __restrict__ eh, float* __restrict__ eres) {
    __shared__ float ms[KK_ * HH_];
    __shared__ float bsh[KK_];
    int n = blockIdx.x, j = threadIdx.x;
    for (int i = j; i < KK_ * HH_; i += 128) ms[i] = m2[i];
    if (j < KK_) bsh[j] = beta[n * KK_ + j];
    __syncthreads();
    float acc = 0.f;
    #pragma unroll
    for (int k = 0; k < KK_; ++k) acc += bsh[k] * ms[k * HH_ + j];
    float v = acc * isdn[n];
    v = v > 0.f ? v : 0.01f * v;
    eh[n * HH_ + j] = v;
    eres[n * HH_ + j] = er[n * HH_ + j] - v;
}

__global__ void final_kernel(const float* __restrict__ ep, const float* __restrict__ eh,
                             const float* __restrict__ ea, const float* __restrict__ Wf,
                             const float* __restrict__ bf, float* __restrict__ out) {
    int n = blockIdx.x, j = threadIdx.x;
    float v = ep[n * HH_ + j] * Wf[j] + eh[n * HH_ + j] * Wf[128 + j] +
              ea[n * HH_ + j] * Wf[256 + j];
    #pragma unroll
    for (int o = 16; o > 0; o >>= 1) v += __shfl_xor_sync(0xffffffffu, v, o);
    __shared__ float red[4];
    if ((j & 31) == 0) red[j >> 5] = v;
    __syncthreads();
    if (j == 0) out[n] = red[0] + red[1] + red[2] + red[3] + bf[0];
}

// ================================ launch ======================================
extern "C" void kernel_launch(void* const* d_in, const int* in_sizes, int n_in,
                              void* d_out, int out_size) {
    const float* x     = (const float*)d_in[0];
    const int*   ind   = (const int*)  d_in[1];
    const float* ln_g  = (const float*)d_in[2];
    const float* ln_b  = (const float*)d_in[3];
    const float* W_ih0 = (const float*)d_in[4];
    const float* W_hh0 = (const float*)d_in[5];
    const float* b_ih0 = (const float*)d_in[6];
    const float* b_hh0 = (const float*)d_in[7];
    const float* W_ih1 = (const float*)d_in[8];
    const float* W_hh1 = (const float*)d_in[9];
    const float* b_ih1 = (const float*)d_in[10];
    const float* b_hh1 = (const float*)d_in[11];
    const float* Wp    = (const float*)d_in[12];
    const float* bp    = (const float*)d_in[13];
    const float* proto = (const float*)d_in[14];
    const float* Ws    = (const float*)d_in[15];
    const float* bs    = (const float*)d_in[16];
    const float* Wa    = (const float*)d_in[17];
    const float* ba    = (const float*)d_in[18];
    const float* Wf    = (const float*)d_in[19];
    const float* bf    = (const float*)d_in[20];
    float* out = (float*)d_out;

    cudaFuncSetAttribute(gemm128, cudaFuncAttributeMaxDynamicSharedMemorySize, (int)GEMM_SMEM);
    cudaFuncSetAttribute(gru_scan, cudaFuncAttributeMaxDynamicSharedMemorySize, (int)SCAN_SMEM);

    float *xn, *xg, *h1, *es, *t1, *ep, *er, *eh, *eres, *ea, *beta, *m1, *m2;
    float *idn, *ide, *isdn, *ide2;
    cudaGetSymbolAddress((void**)&xn,  g_xn);
    cudaGetSymbolAddress((void**)&xg,  g_xg);
    cudaGetSymbolAddress((void**)&h1,  g_h1);
    cudaGetSymbolAddress((void**)&es,  g_es);
    cudaGetSymbolAddress((void**)&t1,  g_t1);
    cudaGetSymbolAddress((void**)&ep,  g_ep);
    cudaGetSymbolAddress((void**)&er,  g_er);
    cudaGetSymbolAddress((void**)&eh,  g_eh);
    cudaGetSymbolAddress((void**)&eres,g_eres);
    cudaGetSymbolAddress((void**)&ea,  g_ea);
    cudaGetSymbolAddress((void**)&beta,g_beta);
    cudaGetSymbolAddress((void**)&m1,  g_m1);
    cudaGetSymbolAddress((void**)&m2,  g_m2);
    cudaGetSymbolAddress((void**)&idn, g_idn);
    cudaGetSymbolAddress((void**)&ide, g_ide);
    cudaGetSymbolAddress((void**)&isdn,g_isdn);
    cudaGetSymbolAddress((void**)&ide2,g_ide2);

    const int MROWS = NN_ * TT_;   // 256000

    // 1. LayerNorm
    ln_kernel<<<MROWS / 8, 256>>>(x, ln_g, ln_b, xn);
    // 2. xg = xn @ W_ih0^T + b_ih0
    gemm128<<<dim3(MROWS / 128, TH_ / 128), 256, GEMM_SMEM>>>(xn, W_ih0, b_ih0, xg, MROWS, TH_, 0);
    // 3. GRU layer 0 -> h1
    gru_scan<<<NN_ / 32, 256, SCAN_SMEM>>>(xg, W_hh0, b_hh0, h1, nullptr);
    // 4. xg = h1 @ W_ih1^T + b_ih1
    gemm128<<<dim3(MROWS / 128, TH_ / 128), 256, GEMM_SMEM>>>(h1, W_ih1, b_ih1, xg, MROWS, TH_, 0);
    // 5. GRU layer 1 -> es (last hidden only)
    gru_scan<<<NN_ / 32, 256, SCAN_SMEM>>>(xg, W_hh1, b_hh1, nullptr, es);
    // 6. t1 = es @ Wp^T
    gemm128<<<dim3((NN_ + 127) / 128, 1), 256, GEMM_SMEM>>>(es, Wp, nullptr, t1, NN_, HH_, 0);
    // 7. degrees
    degrees_kernel<<<1 + (NN_ + 255) / 256, 256>>>(ind, idn, ide);
    // 8-9. prior hconv -> ep, er
    prior_m_kernel<<<EE_, 128>>>(ind, t1, ide, m1);
    prior_out_kernel<<<NN_, 128>>>(ind, m1, idn, bp, es, ep, er);
    // 10. beta + inv-sqrt node degree
    beta_kernel<<<NN_, 128>>>(er, proto, beta, isdn);
    de2_kernel<<<KK_, 256>>>(beta, ide2);
    // 11. t1 = er @ Ws^T + bs
    gemm128<<<dim3((NN_ + 127) / 128, 1), 256, GEMM_SMEM>>>(er, Ws, bs, t1, NN_, HH_, 0);
    // 12-13. soft hconv -> eh, eres
    soft_m_kernel<<<KK_, 128>>>(beta, t1, ide2, m2);
    soft_out_kernel<<<NN_, 128>>>(beta, m2, isdn, er, eh, eres);
    // 14. ea = lrelu(eres @ Wa^T + ba)
    gemm128<<<dim3((NN_ + 127) / 128, 1), 256, GEMM_SMEM>>>(eres, Wa, ba, ea, NN_, HH_, 1);
    // 15. final projection
    final_kernel<<<NN_, 128>>>(ep, eh, ea, Wf, bf, out);
}